// round 10
// baseline (speedup 1.0000x reference)
#include <cuda_runtime.h>
#include <cuda_fp16.h>
#include <cstdint>
#include <cstddef>

#define N_NODES 50000
#define D_IN    128
#define D_HID   256
#define E_MAX   800000

// Scratch (allocation-free rule: __device__ globals)
__device__ __half g_xh  [N_NODES * D_IN];   // fp16 copy of input x
__device__ __half g_comb[N_NODES * D_HID];
__device__ __half g_t1 [N_NODES * D_HID];
__device__ __half g_h0 [N_NODES * D_HID];
__device__ __half g_wq [262144];            // fp16, TRANSPOSED weights [n][k]
__device__ int    g_mode;
__device__ int    g_deg [N_NODES];
__device__ int    g_cur [N_NODES];
__device__ int    g_off [N_NODES + 1];
__device__ int    g_esrc[E_MAX];
__device__ int    g_bsum[256];
__device__ int    g_boff[256];

// ---------------------------------------------------------------------------
// helpers
// ---------------------------------------------------------------------------
__device__ __forceinline__ uint32_t smem_u32(const void* p) {
    uint32_t a;
    asm("{ .reg .u64 t; cvta.to.shared.u64 t, %1; cvt.u32.u64 %0, t; }"
        : "=r"(a) : "l"(p));
    return a;
}

__device__ __forceinline__ void cpa16(uint32_t dst, const void* src, int vbytes) {
    asm volatile("cp.async.cg.shared.global [%0], [%1], 16, %2;"
                 :: "r"(dst), "l"(src), "r"(vbytes));
}
__device__ __forceinline__ void cp_commit() {
    asm volatile("cp.async.commit_group;");
}
template<int NP>
__device__ __forceinline__ void cp_wait() {
    asm volatile("cp.async.wait_group %0;" :: "n"(NP));
}

__device__ __forceinline__ void ldm4(uint32_t* r, uint32_t addr) {
    asm volatile("ldmatrix.sync.aligned.m8n8.x4.shared.b16 {%0,%1,%2,%3}, [%4];"
                 : "=r"(r[0]), "=r"(r[1]), "=r"(r[2]), "=r"(r[3]) : "r"(addr));
}

__device__ __forceinline__ void mma16(float* c, const uint32_t* a, const uint32_t* b) {
    asm volatile(
        "mma.sync.aligned.m16n8k16.row.col.f32.f16.f16.f32 "
        "{%0,%1,%2,%3}, {%4,%5,%6,%7}, {%8,%9}, {%0,%1,%2,%3};\n"
        : "+f"(c[0]), "+f"(c[1]), "+f"(c[2]), "+f"(c[3])
        : "r"(a[0]), "r"(a[1]), "r"(a[2]), "r"(a[3]), "r"(b[0]), "r"(b[1]));
}

// ---------------------------------------------------------------------------
// Edge-index dtype detect (harness may deliver int64 as int32)
// ---------------------------------------------------------------------------
__global__ void detect_kernel(const void* __restrict__ ei_raw, int nscan) {
    if (threadIdx.x == 0 && blockIdx.x == 0) {
        const long long* p = (const long long*)ei_raw;
        int is64 = 1;
        for (int i = 0; i < nscan; i++) {
            long long v = p[i];
            if (v < 0 || v >= N_NODES) { is64 = 0; break; }
        }
        g_mode = is64;
    }
}

__device__ __forceinline__ int edge_at(const void* raw, long long idx) {
    return g_mode ? (int)((const long long*)raw)[idx] : ((const int*)raw)[idx];
}

// ---------------------------------------------------------------------------
// CSR build
// ---------------------------------------------------------------------------
__global__ void zero_int_kernel(int* __restrict__ p, int n) {
    int i = blockIdx.x * blockDim.x + threadIdx.x;
    if (i < n) p[i] = 0;
}

__global__ void hist_kernel(const void* __restrict__ raw, int* __restrict__ deg, int E) {
    int e = blockIdx.x * blockDim.x + threadIdx.x;
    if (e >= E) return;
    atomicAdd(&deg[edge_at(raw, (long long)E + e)], 1);
}

#define SCAN_B 256
#define SCAN_NB ((N_NODES + SCAN_B - 1) / SCAN_B)   // 196

__global__ __launch_bounds__(SCAN_B)
void scan_p1(const int* __restrict__ deg, int* __restrict__ bsum) {
    __shared__ int sh[SCAN_B];
    int i = blockIdx.x * SCAN_B + threadIdx.x;
    sh[threadIdx.x] = (i < N_NODES) ? deg[i] : 0;
    __syncthreads();
    for (int d = SCAN_B / 2; d > 0; d >>= 1) {
        if (threadIdx.x < d) sh[threadIdx.x] += sh[threadIdx.x + d];
        __syncthreads();
    }
    if (threadIdx.x == 0) bsum[blockIdx.x] = sh[0];
}

__global__ __launch_bounds__(256)
void scan_p2(const int* __restrict__ bsum, int* __restrict__ boff) {
    __shared__ int sh[256];
    int t = threadIdx.x;
    sh[t] = (t < SCAN_NB) ? bsum[t] : 0;
    __syncthreads();
    for (int d = 1; d < 256; d <<= 1) {
        int v = (t >= d) ? sh[t - d] : 0;
        __syncthreads();
        sh[t] += v;
        __syncthreads();
    }
    if (t < SCAN_NB) boff[t] = (t == 0) ? 0 : sh[t - 1];
}

__global__ __launch_bounds__(SCAN_B)
void scan_p3(const int* __restrict__ deg, const int* __restrict__ boff,
             int* __restrict__ off, int* __restrict__ cursor) {
    __shared__ int sh[SCAN_B];
    int i = blockIdx.x * SCAN_B + threadIdx.x;
    int t = threadIdx.x;
    int v = (i < N_NODES) ? deg[i] : 0;
    sh[t] = v;
    __syncthreads();
    for (int d = 1; d < SCAN_B; d <<= 1) {
        int u = (t >= d) ? sh[t - d] : 0;
        __syncthreads();
        sh[t] += u;
        __syncthreads();
    }
    int base = boff[blockIdx.x];
    if (i < N_NODES) {
        int incl = base + sh[t];
        off[i + 1] = incl;
        cursor[i]  = incl - v;
        if (i == 0) off[0] = 0;
    }
}

__global__ void fill_kernel(const void* __restrict__ raw, int* __restrict__ cursor,
                            int* __restrict__ esrc, int E) {
    int e = blockIdx.x * blockDim.x + threadIdx.x;
    if (e >= E) return;
    int src = edge_at(raw, e);
    int dst = edge_at(raw, (long long)E + e);
    int pos = atomicAdd(&cursor[dst], 1);
    esrc[pos] = src;
}

// ---------------------------------------------------------------------------
// x -> fp16 (one launch)
// ---------------------------------------------------------------------------
__global__ void quantx_kernel(const float2* __restrict__ x, __half2* __restrict__ xh, int n2) {
    int i = blockIdx.x * blockDim.x + threadIdx.x;
    if (i >= n2) return;
    float2 v = __ldg(x + i);
    xh[i] = __floats2half2_rn(v.x, v.y);
}

// ---------------------------------------------------------------------------
// Weight transpose + fp16 quantize (one launch, all 5 matrices)
// ---------------------------------------------------------------------------
__global__ void quantw_all(const float* __restrict__ w10, const float* __restrict__ w20,
                           const float* __restrict__ w11, const float* __restrict__ w21,
                           const float* __restrict__ wo,  __half* __restrict__ dst) {
    int i = blockIdx.x * blockDim.x + threadIdx.x;
    if (i >= 262144) return;
    const float* src;
    int d, K, N;
    if      (i < 32768)  { src = w10; d = i;          K = 128; N = 256; }
    else if (i < 98304)  { src = w20; d = i - 32768;  K = 256; N = 256; }
    else if (i < 163840) { src = w11; d = i - 98304;  K = 256; N = 256; }
    else if (i < 229376) { src = w21; d = i - 163840; K = 256; N = 256; }
    else                 { src = wo;  d = i - 229376; K = 256; N = 128; }
    int n = d / K, k = d - n * K;
    dst[i] = __float2half_rn(src[(size_t)k * N + n]);
}

// ---------------------------------------------------------------------------
// Gather + GIN combine from fp16 input, fp32 accumulate, fp16 output.
// DH = 128 (lane: uint2 = 4 halves) or 256 (lane: uint4 = 8 halves).
// ---------------------------------------------------------------------------
template<int DH>
__global__ __launch_bounds__(256)
void gather_h(const __half* __restrict__ x,
              const int* __restrict__ off,
              const int* __restrict__ esrc,
              const float* __restrict__ epsp,
              __half* __restrict__ out) {
    constexpr int NH = DH / 32;          // halves per lane: 4 or 8
    int node = blockIdx.x * 8 + (threadIdx.x >> 5);
    if (node >= N_NODES) return;
    int lane = threadIdx.x & 31;
    float scale = 1.f + __ldg(epsp);
    int s = off[node], e = off[node + 1];

    float acc[NH];
    #pragma unroll
    for (int j = 0; j < NH; j++) acc[j] = 0.f;

    auto accum = [&](const __half* row, float sc, bool fma) {
        if (NH == 4) {
            uint2 v = __ldg(reinterpret_cast<const uint2*>(row) + lane);
            const __half2* hp = reinterpret_cast<const __half2*>(&v);
            #pragma unroll
            for (int j = 0; j < 2; j++) {
                float2 f = __half22float2(hp[j]);
                if (fma) {
                    acc[2*j]   = fmaf(sc, f.x, acc[2*j]);
                    acc[2*j+1] = fmaf(sc, f.y, acc[2*j+1]);
                } else {
                    acc[2*j] += f.x; acc[2*j+1] += f.y;
                }
            }
        } else {
            uint4 v = __ldg(reinterpret_cast<const uint4*>(row) + lane);
            const __half2* hp = reinterpret_cast<const __half2*>(&v);
            #pragma unroll
            for (int j = 0; j < 4; j++) {
                float2 f = __half22float2(hp[j]);
                if (fma) {
                    acc[2*j]   = fmaf(sc, f.x, acc[2*j]);
                    acc[2*j+1] = fmaf(sc, f.y, acc[2*j+1]);
                } else {
                    acc[2*j] += f.x; acc[2*j+1] += f.y;
                }
            }
        }
    };

    int i = s;
    for (; i + 1 < e; i += 2) {
        accum(x + (size_t)esrc[i]     * DH, 1.f, false);
        accum(x + (size_t)esrc[i + 1] * DH, 1.f, false);
    }
    if (i < e) accum(x + (size_t)esrc[i] * DH, 1.f, false);
    accum(x + (size_t)node * DH, scale, true);

    // pack + store
    if (NH == 4) {
        __half2 p0 = __floats2half2_rn(acc[0], acc[1]);
        __half2 p1 = __floats2half2_rn(acc[2], acc[3]);
        uint2 pk = make_uint2(*(uint32_t*)&p0, *(uint32_t*)&p1);
        *(reinterpret_cast<uint2*>(out + (size_t)node * DH) + lane) = pk;
    } else {
        __half2 p0 = __floats2half2_rn(acc[0], acc[1]);
        __half2 p1 = __floats2half2_rn(acc[2], acc[3]);
        __half2 p2 = __floats2half2_rn(acc[4], acc[5]);
        __half2 p3 = __floats2half2_rn(acc[6], acc[7]);
        uint4 pk;
        pk.x = *(uint32_t*)&p0; pk.y = *(uint32_t*)&p1;
        pk.z = *(uint32_t*)&p2; pk.w = *(uint32_t*)&p3;
        *(reinterpret_cast<uint4*>(out + (size_t)node * DH) + lane) = pk;
    }
}

// ---------------------------------------------------------------------------
// FP16 mma.sync GEMM (m16n8k16), ldmatrix fragments, 4-stage cp.async.
//   C = op(A @ Wt^T + bias);  BM=128, BN=128, BK=32; 256 thr (4m x 2n warps).
//   Smem rows pitch 80B -> ldmatrix conflict-free.
// ---------------------------------------------------------------------------
#define APITCH   80
#define ASTG_B   (128 * APITCH)             // 10240 bytes
#define STG_B    (2 * ASTG_B)               // 20480: A + B per stage
#define NSTAGE   4
#define GEMM_SMEM_BYTES (NSTAGE * STG_B)    // 81920

template<bool RELU, bool OUT16>
__global__ __launch_bounds__(256, 2)
void gemm_fp16(const __half* __restrict__ A,
               const __half* __restrict__ Wt,     // [Ntot][K]
               const float* __restrict__ bias,
               void* __restrict__ Cv,
               int M, int K, int Ncol) {
    extern __shared__ char dsm[];
    const uint32_t sbase = smem_u32(dsm);

    const int tid  = threadIdx.x;
    const int lane = tid & 31;
    const int warp = tid >> 5;
    const int wm   = warp >> 1;
    const int wn   = warp & 1;
    const int gid  = lane >> 2;
    const int tig  = lane & 3;

    const int row0 = blockIdx.x * 128;
    const int col0 = blockIdx.y * 128;

    float acc[2][8][4];
    #pragma unroll
    for (int mt = 0; mt < 2; mt++)
        #pragma unroll
        for (int nt = 0; nt < 8; nt++)
            #pragma unroll
            for (int i = 0; i < 4; i++)
                acc[mt][nt][i] = 0.f;

    const int a_lrow = lane & 15;
    const int a_kext = (lane & 16) ? 16 : 0;
    const int b_lrow = (lane & 7) + ((lane & 16) ? 8 : 0);
    const int b_kext = (lane & 8) ? 16 : 0;

    auto issue = [&](int c) {
        const int k0  = c * 32;
        const int stg = c % NSTAGE;
        const uint32_t abase = sbase + stg * STG_B;
        #pragma unroll
        for (int i = 0; i < 2; i++) {
            int chunk = tid + 256 * i;            // 0..511
            int row = chunk >> 2, cs = chunk & 3;
            bool ok = (row0 + row) < M;
            const __half* src = ok ? (A + (size_t)(row0 + row) * K + k0 + cs * 8) : A;
            cpa16(abase + row * APITCH + cs * 16, src, ok ? 16 : 0);
        }
        const uint32_t bbase = abase + ASTG_B;
        #pragma unroll
        for (int i = 0; i < 2; i++) {
            int chunk = tid + 256 * i;
            int n = chunk >> 2, cs = chunk & 3;
            const __half* src = Wt + (size_t)(col0 + n) * K + k0 + cs * 8;
            cpa16(bbase + n * APITCH + cs * 16, src, 16);
        }
    };

    auto compute = [&](int c) {
        const int stg = c % NSTAGE;
        const uint32_t abase = sbase + stg * STG_B;
        const uint32_t bbase = abase + ASTG_B;
        #pragma unroll
        for (int ks = 0; ks < 2; ks++) {
            uint32_t af[2][4];
            #pragma unroll
            for (int mt = 0; mt < 2; mt++) {
                int r = wm * 32 + mt * 16 + a_lrow;
                ldm4(af[mt], abase + r * APITCH + ks * 32 + a_kext);
            }
            uint32_t bf[8][2];
            #pragma unroll
            for (int np = 0; np < 4; np++) {
                int n = wn * 64 + np * 16 + b_lrow;
                uint32_t r4[4];
                ldm4(r4, bbase + n * APITCH + ks * 32 + b_kext);
                bf[2 * np][0]     = r4[0];
                bf[2 * np][1]     = r4[1];
                bf[2 * np + 1][0] = r4[2];
                bf[2 * np + 1][1] = r4[3];
            }
            #pragma unroll
            for (int mt = 0; mt < 2; mt++)
                #pragma unroll
                for (int nt = 0; nt < 8; nt++)
                    mma16(acc[mt][nt], af[mt], bf[nt]);
        }
    };

    const int NC = K / 32;
    issue(0); cp_commit();
    issue(1); cp_commit();
    issue(2); cp_commit();

    for (int c = 0; c < NC; c++) {
        cp_wait<2>();
        __syncthreads();
        if (c + 3 < NC) issue(c + 3);
        cp_commit();
        compute(c);
    }

    // ---- epilogue ----
    #pragma unroll
    for (int nt = 0; nt < 8; nt++) {
        int col = col0 + wn * 64 + nt * 8 + 2 * tig;
        float b0 = __ldg(bias + col);
        float b1 = __ldg(bias + col + 1);
        #pragma unroll
        for (int mt = 0; mt < 2; mt++) {
            int r = row0 + wm * 32 + mt * 16 + gid;
            float v0 = acc[mt][nt][0] + b0;
            float v1 = acc[mt][nt][1] + b1;
            float v2 = acc[mt][nt][2] + b0;
            float v3 = acc[mt][nt][3] + b1;
            if (RELU) {
                v0 = fmaxf(v0, 0.f); v1 = fmaxf(v1, 0.f);
                v2 = fmaxf(v2, 0.f); v3 = fmaxf(v3, 0.f);
            }
            if (OUT16) {
                __half* C = (__half*)Cv;
                if (r < M) {
                    __half2 h = __floats2half2_rn(v0, v1);
                    *reinterpret_cast<__half2*>(C + (size_t)r * Ncol + col) = h;
                }
                if (r + 8 < M) {
                    __half2 h = __floats2half2_rn(v2, v3);
                    *reinterpret_cast<__half2*>(C + (size_t)(r + 8) * Ncol + col) = h;
                }
            } else {
                float* C = (float*)Cv;
                if (r < M)
                    *reinterpret_cast<float2*>(C + (size_t)r * Ncol + col) = make_float2(v0, v1);
                if (r + 8 < M)
                    *reinterpret_cast<float2*>(C + (size_t)(r + 8) * Ncol + col) = make_float2(v2, v3);
            }
        }
    }
}

// ---------------------------------------------------------------------------
// Launch
// ---------------------------------------------------------------------------
extern "C" void kernel_launch(void* const* d_in, const int* in_sizes, int n_in,
                              void* d_out, int out_size) {
    const float* x    = (const float*)d_in[0];
    const void*  eiRaw= d_in[1];
    const float* eps0 = (const float*)d_in[2];
    const float* W1_0 = (const float*)d_in[3];
    const float* b1_0 = (const float*)d_in[4];
    const float* W2_0 = (const float*)d_in[5];
    const float* b2_0 = (const float*)d_in[6];
    const float* eps1 = (const float*)d_in[7];
    const float* W1_1 = (const float*)d_in[8];
    const float* b1_1 = (const float*)d_in[9];
    const float* W2_1 = (const float*)d_in[10];
    const float* b2_1 = (const float*)d_in[11];
    const float* Wo   = (const float*)d_in[12];
    const float* bo   = (const float*)d_in[13];
    float*       out  = (float*)d_out;

    const int two_e = in_sizes[1];
    const int E     = two_e / 2;

    __half *xh, *comb, *t1, *h0, *wq;
    int *deg, *cur, *off, *esrc, *bsum, *boff;
    cudaGetSymbolAddress((void**)&xh,   g_xh);
    cudaGetSymbolAddress((void**)&comb, g_comb);
    cudaGetSymbolAddress((void**)&t1,   g_t1);
    cudaGetSymbolAddress((void**)&h0,   g_h0);
    cudaGetSymbolAddress((void**)&wq,   g_wq);
    cudaGetSymbolAddress((void**)&deg,  g_deg);
    cudaGetSymbolAddress((void**)&cur,  g_cur);
    cudaGetSymbolAddress((void**)&off,  g_off);
    cudaGetSymbolAddress((void**)&esrc, g_esrc);
    cudaGetSymbolAddress((void**)&bsum, g_bsum);
    cudaGetSymbolAddress((void**)&boff, g_boff);

    __half* W1_0t = wq;                   // [256][128]
    __half* W2_0t = wq + 32768;           // [256][256]
    __half* W1_1t = wq + 98304;           // [256][256]
    __half* W2_1t = wq + 163840;          // [256][256]
    __half* Wot   = wq + 229376;          // [128][256]

    cudaFuncSetAttribute(gemm_fp16<true,  true >,
                         cudaFuncAttributeMaxDynamicSharedMemorySize, GEMM_SMEM_BYTES);
    cudaFuncSetAttribute(gemm_fp16<false, true >,
                         cudaFuncAttributeMaxDynamicSharedMemorySize, GEMM_SMEM_BYTES);
    cudaFuncSetAttribute(gemm_fp16<false, false>,
                         cudaFuncAttributeMaxDynamicSharedMemorySize, GEMM_SMEM_BYTES);

    // ---- detect edge dtype ----
    int nscan = two_e < 128 ? two_e : 128;
    detect_kernel<<<1, 32>>>(eiRaw, nscan);

    // ---- CSR build ----
    zero_int_kernel<<<(N_NODES + 255) / 256, 256>>>(deg, N_NODES);
    hist_kernel<<<(E + 255) / 256, 256>>>(eiRaw, deg, E);
    scan_p1<<<SCAN_NB, SCAN_B>>>(deg, bsum);
    scan_p2<<<1, 256>>>(bsum, boff);
    scan_p3<<<SCAN_NB, SCAN_B>>>(deg, boff, off, cur);
    fill_kernel<<<(E + 255) / 256, 256>>>(eiRaw, cur, esrc, E);

    // ---- quantize: x -> fp16, weights -> fp16 transposed ----
    quantx_kernel<<<(N_NODES * D_IN / 2 + 255) / 256, 256>>>((const float2*)x, (__half2*)xh,
                                                             N_NODES * D_IN / 2);
    quantw_all<<<1024, 256>>>(W1_0, W2_0, W1_1, W2_1, Wo, wq);

    dim3 gH((N_NODES + 127) / 128, 2);   // Ncol=256
    dim3 gO((N_NODES + 127) / 128, 1);   // Ncol=128
    int  gGather = (N_NODES + 7) / 8;

    // ---- layer 0 ----
    gather_h<128><<<gGather, 256>>>(xh, off, esrc, eps0, comb);
    gemm_fp16<true,  true ><<<gH, 256, GEMM_SMEM_BYTES>>>(comb, W1_0t, b1_0, t1, N_NODES, D_IN,  D_HID);
    gemm_fp16<false, true ><<<gH, 256, GEMM_SMEM_BYTES>>>(t1,   W2_0t, b2_0, h0, N_NODES, D_HID, D_HID);

    // ---- layer 1 ----
    gather_h<256><<<gGather, 256>>>(h0, off, esrc, eps1, comb);
    gemm_fp16<true,  true ><<<gH, 256, GEMM_SMEM_BYTES>>>(comb, W1_1t, b1_1, t1, N_NODES, D_HID, D_HID);
    gemm_fp16<false, true ><<<gH, 256, GEMM_SMEM_BYTES>>>(t1,   W2_1t, b2_1, h0, N_NODES, D_HID, D_HID); // h1

    // ---- fc_out (fp32 out) ----
    gemm_fp16<false, false><<<gO, 256, GEMM_SMEM_BYTES>>>(h0, Wot, bo, out, N_NODES, D_HID, D_IN);
}

// round 14
// speedup vs baseline: 1.0154x; 1.0154x over previous
#include <cuda_runtime.h>
#include <cuda_fp16.h>
#include <cstdint>
#include <cstddef>

#define N_NODES 50000
#define D_IN    128
#define D_HID   256
#define E_MAX   800000

// Scratch (allocation-free rule: __device__ globals)
__device__ __half g_xh  [N_NODES * D_IN];   // fp16 copy of input x
__device__ __half g_comb[N_NODES * D_HID];
__device__ __half g_t1 [N_NODES * D_HID];
__device__ __half g_h0 [N_NODES * D_HID];
__device__ __half g_wq [262144];            // fp16, TRANSPOSED weights [n][k]
__device__ int    g_mode;
__device__ int    g_deg [N_NODES];
__device__ int    g_cur [N_NODES];
__device__ int    g_off [N_NODES + 1];
__device__ int    g_esrc[E_MAX];
__device__ int    g_bsum[256];
__device__ int    g_boff[256];

// ---------------------------------------------------------------------------
// helpers
// ---------------------------------------------------------------------------
__device__ __forceinline__ uint32_t smem_u32(const void* p) {
    uint32_t a;
    asm("{ .reg .u64 t; cvta.to.shared.u64 t, %1; cvt.u32.u64 %0, t; }"
        : "=r"(a) : "l"(p));
    return a;
}

__device__ __forceinline__ void cpa16(uint32_t dst, const void* src, int vbytes) {
    asm volatile("cp.async.cg.shared.global [%0], [%1], 16, %2;"
                 :: "r"(dst), "l"(src), "r"(vbytes));
}
__device__ __forceinline__ void cp_commit() {
    asm volatile("cp.async.commit_group;");
}
template<int NP>
__device__ __forceinline__ void cp_wait() {
    asm volatile("cp.async.wait_group %0;" :: "n"(NP));
}

__device__ __forceinline__ void ldm4(uint32_t* r, uint32_t addr) {
    asm volatile("ldmatrix.sync.aligned.m8n8.x4.shared.b16 {%0,%1,%2,%3}, [%4];"
                 : "=r"(r[0]), "=r"(r[1]), "=r"(r[2]), "=r"(r[3]) : "r"(addr));
}

__device__ __forceinline__ void mma16(float* c, const uint32_t* a, const uint32_t* b) {
    asm volatile(
        "mma.sync.aligned.m16n8k16.row.col.f32.f16.f16.f32 "
        "{%0,%1,%2,%3}, {%4,%5,%6,%7}, {%8,%9}, {%0,%1,%2,%3};\n"
        : "+f"(c[0]), "+f"(c[1]), "+f"(c[2]), "+f"(c[3])
        : "r"(a[0]), "r"(a[1]), "r"(a[2]), "r"(a[3]), "r"(b[0]), "r"(b[1]));
}

// ---------------------------------------------------------------------------
// Edge-index dtype detect (harness may deliver int64 as int32)
// ---------------------------------------------------------------------------
__global__ void detect_kernel(const void* __restrict__ ei_raw, int nscan) {
    if (threadIdx.x == 0 && blockIdx.x == 0) {
        const long long* p = (const long long*)ei_raw;
        int is64 = 1;
        for (int i = 0; i < nscan; i++) {
            long long v = p[i];
            if (v < 0 || v >= N_NODES) { is64 = 0; break; }
        }
        g_mode = is64;
    }
}

__device__ __forceinline__ int edge_at(const void* raw, long long idx) {
    return g_mode ? (int)((const long long*)raw)[idx] : ((const int*)raw)[idx];
}

// ---------------------------------------------------------------------------
// CSR build
// ---------------------------------------------------------------------------
__global__ void zero_int_kernel(int* __restrict__ p, int n) {
    int i = blockIdx.x * blockDim.x + threadIdx.x;
    if (i < n) p[i] = 0;
}

__global__ void hist_kernel(const void* __restrict__ raw, int* __restrict__ deg, int E) {
    int e = blockIdx.x * blockDim.x + threadIdx.x;
    if (e >= E) return;
    atomicAdd(&deg[edge_at(raw, (long long)E + e)], 1);
}

#define SCAN_B 256
#define SCAN_NB ((N_NODES + SCAN_B - 1) / SCAN_B)   // 196

__global__ __launch_bounds__(SCAN_B)
void scan_p1(const int* __restrict__ deg, int* __restrict__ bsum) {
    __shared__ int sh[SCAN_B];
    int i = blockIdx.x * SCAN_B + threadIdx.x;
    sh[threadIdx.x] = (i < N_NODES) ? deg[i] : 0;
    __syncthreads();
    for (int d = SCAN_B / 2; d > 0; d >>= 1) {
        if (threadIdx.x < d) sh[threadIdx.x] += sh[threadIdx.x + d];
        __syncthreads();
    }
    if (threadIdx.x == 0) bsum[blockIdx.x] = sh[0];
}

__global__ __launch_bounds__(256)
void scan_p2(const int* __restrict__ bsum, int* __restrict__ boff) {
    __shared__ int sh[256];
    int t = threadIdx.x;
    sh[t] = (t < SCAN_NB) ? bsum[t] : 0;
    __syncthreads();
    for (int d = 1; d < 256; d <<= 1) {
        int v = (t >= d) ? sh[t - d] : 0;
        __syncthreads();
        sh[t] += v;
        __syncthreads();
    }
    if (t < SCAN_NB) boff[t] = (t == 0) ? 0 : sh[t - 1];
}

__global__ __launch_bounds__(SCAN_B)
void scan_p3(const int* __restrict__ deg, const int* __restrict__ boff,
             int* __restrict__ off, int* __restrict__ cursor) {
    __shared__ int sh[SCAN_B];
    int i = blockIdx.x * SCAN_B + threadIdx.x;
    int t = threadIdx.x;
    int v = (i < N_NODES) ? deg[i] : 0;
    sh[t] = v;
    __syncthreads();
    for (int d = 1; d < SCAN_B; d <<= 1) {
        int u = (t >= d) ? sh[t - d] : 0;
        __syncthreads();
        sh[t] += u;
        __syncthreads();
    }
    int base = boff[blockIdx.x];
    if (i < N_NODES) {
        int incl = base + sh[t];
        off[i + 1] = incl;
        cursor[i]  = incl - v;
        if (i == 0) off[0] = 0;
    }
}

__global__ void fill_kernel(const void* __restrict__ raw, int* __restrict__ cursor,
                            int* __restrict__ esrc, int E) {
    int e = blockIdx.x * blockDim.x + threadIdx.x;
    if (e >= E) return;
    int src = edge_at(raw, e);
    int dst = edge_at(raw, (long long)E + e);
    int pos = atomicAdd(&cursor[dst], 1);
    esrc[pos] = src;
}

// ---------------------------------------------------------------------------
// x -> fp16 (one launch)
// ---------------------------------------------------------------------------
__global__ void quantx_kernel(const float2* __restrict__ x, __half2* __restrict__ xh, int n2) {
    int i = blockIdx.x * blockDim.x + threadIdx.x;
    if (i >= n2) return;
    float2 v = __ldg(x + i);
    xh[i] = __floats2half2_rn(v.x, v.y);
}

// ---------------------------------------------------------------------------
// Weight transpose + fp16 quantize (one launch, all 5 matrices)
// ---------------------------------------------------------------------------
__global__ void quantw_all(const float* __restrict__ w10, const float* __restrict__ w20,
                           const float* __restrict__ w11, const float* __restrict__ w21,
                           const float* __restrict__ wo,  __half* __restrict__ dst) {
    int i = blockIdx.x * blockDim.x + threadIdx.x;
    if (i >= 262144) return;
    const float* src;
    int d, K, N;
    if      (i < 32768)  { src = w10; d = i;          K = 128; N = 256; }
    else if (i < 98304)  { src = w20; d = i - 32768;  K = 256; N = 256; }
    else if (i < 163840) { src = w11; d = i - 98304;  K = 256; N = 256; }
    else if (i < 229376) { src = w21; d = i - 163840; K = 256; N = 256; }
    else                 { src = wo;  d = i - 229376; K = 256; N = 128; }
    int n = d / K, k = d - n * K;
    dst[i] = __float2half_rn(src[(size_t)k * N + n]);
}

// ---------------------------------------------------------------------------
// Gather + GIN combine from fp16 input, fp32 accumulate, fp16 output.
// DH = 128 (lane: uint2) or 256 (lane: uint4). 4-edge unrolled for MLP=4.
// ---------------------------------------------------------------------------
__device__ __forceinline__ void add_u2(float* acc, uint2 v) {
    const __half2* hp = reinterpret_cast<const __half2*>(&v);
    #pragma unroll
    for (int j = 0; j < 2; j++) {
        float2 f = __half22float2(hp[j]);
        acc[2 * j] += f.x; acc[2 * j + 1] += f.y;
    }
}
__device__ __forceinline__ void add_u4(float* acc, uint4 v) {
    const __half2* hp = reinterpret_cast<const __half2*>(&v);
    #pragma unroll
    for (int j = 0; j < 4; j++) {
        float2 f = __half22float2(hp[j]);
        acc[2 * j] += f.x; acc[2 * j + 1] += f.y;
    }
}

template<int DH>
__global__ __launch_bounds__(256)
void gather_h(const __half* __restrict__ x,
              const int* __restrict__ off,
              const int* __restrict__ esrc,
              const float* __restrict__ epsp,
              __half* __restrict__ out) {
    constexpr int NH = DH / 32;          // halves per lane: 4 or 8
    int node = blockIdx.x * 8 + (threadIdx.x >> 5);
    if (node >= N_NODES) return;
    int lane = threadIdx.x & 31;
    float scale = 1.f + __ldg(epsp);
    int s = off[node], e = off[node + 1];

    float acc[NH];
    #pragma unroll
    for (int j = 0; j < NH; j++) acc[j] = 0.f;

    int i = s;
    if (NH == 4) {
        const uint2* xp = reinterpret_cast<const uint2*>(x);
        for (; i + 3 < e; i += 4) {
            int s0 = esrc[i], s1 = esrc[i + 1], s2 = esrc[i + 2], s3 = esrc[i + 3];
            uint2 v0 = __ldg(xp + (size_t)s0 * 32 + lane);
            uint2 v1 = __ldg(xp + (size_t)s1 * 32 + lane);
            uint2 v2 = __ldg(xp + (size_t)s2 * 32 + lane);
            uint2 v3 = __ldg(xp + (size_t)s3 * 32 + lane);
            add_u2(acc, v0); add_u2(acc, v1); add_u2(acc, v2); add_u2(acc, v3);
        }
        for (; i < e; i++)
            add_u2(acc, __ldg(xp + (size_t)esrc[i] * 32 + lane));
        // self term
        {
            uint2 v = __ldg(xp + (size_t)node * 32 + lane);
            const __half2* hp = reinterpret_cast<const __half2*>(&v);
            #pragma unroll
            for (int j = 0; j < 2; j++) {
                float2 f = __half22float2(hp[j]);
                acc[2 * j]     = fmaf(scale, f.x, acc[2 * j]);
                acc[2 * j + 1] = fmaf(scale, f.y, acc[2 * j + 1]);
            }
        }
        __half2 p0 = __floats2half2_rn(acc[0], acc[1]);
        __half2 p1 = __floats2half2_rn(acc[2], acc[3]);
        uint2 pk = make_uint2(*(uint32_t*)&p0, *(uint32_t*)&p1);
        *(reinterpret_cast<uint2*>(out + (size_t)node * DH) + lane) = pk;
    } else {
        const uint4* xp = reinterpret_cast<const uint4*>(x);
        for (; i + 3 < e; i += 4) {
            int s0 = esrc[i], s1 = esrc[i + 1], s2 = esrc[i + 2], s3 = esrc[i + 3];
            uint4 v0 = __ldg(xp + (size_t)s0 * 32 + lane);
            uint4 v1 = __ldg(xp + (size_t)s1 * 32 + lane);
            uint4 v2 = __ldg(xp + (size_t)s2 * 32 + lane);
            uint4 v3 = __ldg(xp + (size_t)s3 * 32 + lane);
            add_u4(acc, v0); add_u4(acc, v1); add_u4(acc, v2); add_u4(acc, v3);
        }
        for (; i < e; i++)
            add_u4(acc, __ldg(xp + (size_t)esrc[i] * 32 + lane));
        {
            uint4 v = __ldg(xp + (size_t)node * 32 + lane);
            const __half2* hp = reinterpret_cast<const __half2*>(&v);
            #pragma unroll
            for (int j = 0; j < 4; j++) {
                float2 f = __half22float2(hp[j]);
                acc[2 * j]     = fmaf(scale, f.x, acc[2 * j]);
                acc[2 * j + 1] = fmaf(scale, f.y, acc[2 * j + 1]);
            }
        }
        __half2 p0 = __floats2half2_rn(acc[0], acc[1]);
        __half2 p1 = __floats2half2_rn(acc[2], acc[3]);
        __half2 p2 = __floats2half2_rn(acc[4], acc[5]);
        __half2 p3 = __floats2half2_rn(acc[6], acc[7]);
        uint4 pk;
        pk.x = *(uint32_t*)&p0; pk.y = *(uint32_t*)&p1;
        pk.z = *(uint32_t*)&p2; pk.w = *(uint32_t*)&p3;
        *(reinterpret_cast<uint4*>(out + (size_t)node * DH) + lane) = pk;
    }
}

// ---------------------------------------------------------------------------
// FP16 mma.sync GEMM (m16n8k16), ldmatrix fragments, 3-stage cp.async (R9).
//   C = op(A @ Wt^T + bias);  BM=128, BN=128, BK=32; 256 thr (4m x 2n warps).
//   Smem rows pitch 80B -> ldmatrix conflict-free.
// ---------------------------------------------------------------------------
#define APITCH   80
#define ASTG_B   (128 * APITCH)             // 10240 bytes
#define STG_B    (2 * ASTG_B)               // 20480: A + B per stage
#define GEMM_SMEM_BYTES (3 * STG_B)         // 61440

template<bool RELU, bool OUT16>
__global__ __launch_bounds__(256, 2)
void gemm_fp16(const __half* __restrict__ A,
               const __half* __restrict__ Wt,     // [Ntot][K]
               const float* __restrict__ bias,
               void* __restrict__ Cv,
               int M, int K, int Ncol) {
    extern __shared__ char dsm[];
    const uint32_t sbase = smem_u32(dsm);

    const int tid  = threadIdx.x;
    const int lane = tid & 31;
    const int warp = tid >> 5;
    const int wm   = warp >> 1;
    const int wn   = warp & 1;
    const int gid  = lane >> 2;
    const int tig  = lane & 3;

    const int row0 = blockIdx.x * 128;
    const int col0 = blockIdx.y * 128;

    float acc[2][8][4];
    #pragma unroll
    for (int mt = 0; mt < 2; mt++)
        #pragma unroll
        for (int nt = 0; nt < 8; nt++)
            #pragma unroll
            for (int i = 0; i < 4; i++)
                acc[mt][nt][i] = 0.f;

    const int a_lrow = lane & 15;
    const int a_kext = (lane & 16) ? 16 : 0;
    const int b_lrow = (lane & 7) + ((lane & 16) ? 8 : 0);
    const int b_kext = (lane & 8) ? 16 : 0;

    auto issue = [&](int c) {
        const int k0  = c * 32;
        const int stg = c % 3;
        const uint32_t abase = sbase + stg * STG_B;
        #pragma unroll
        for (int i = 0; i < 2; i++) {
            int chunk = tid + 256 * i;            // 0..511
            int row = chunk >> 2, cs = chunk & 3;
            bool ok = (row0 + row) < M;
            const __half* src = ok ? (A + (size_t)(row0 + row) * K + k0 + cs * 8) : A;
            cpa16(abase + row * APITCH + cs * 16, src, ok ? 16 : 0);
        }
        const uint32_t bbase = abase + ASTG_B;
        #pragma unroll
        for (int i = 0; i < 2; i++) {
            int chunk = tid + 256 * i;
            int n = chunk >> 2, cs = chunk & 3;
            const __half* src = Wt + (size_t)(col0 + n) * K + k0 + cs * 8;
            cpa16(bbase + n * APITCH + cs * 16, src, 16);
        }
    };

    auto compute = [&](int c) {
        const int stg = c % 3;
        const uint32_t abase = sbase + stg * STG_B;
        const uint32_t bbase = abase + ASTG_B;
        #pragma unroll
        for (int ks = 0; ks < 2; ks++) {
            uint32_t af[2][4];
            #pragma unroll
            for (int mt = 0; mt < 2; mt++) {
                int r = wm * 32 + mt * 16 + a_lrow;
                ldm4(af[mt], abase + r * APITCH + ks * 32 + a_kext);
            }
            uint32_t bf[8][2];
            #pragma unroll
            for (int np = 0; np < 4; np++) {
                int n = wn * 64 + np * 16 + b_lrow;
                uint32_t r4[4];
                ldm4(r4, bbase + n * APITCH + ks * 32 + b_kext);
                bf[2 * np][0]     = r4[0];
                bf[2 * np][1]     = r4[1];
                bf[2 * np + 1][0] = r4[2];
                bf[2 * np + 1][1] = r4[3];
            }
            #pragma unroll
            for (int mt = 0; mt < 2; mt++)
                #pragma unroll
                for (int nt = 0; nt < 8; nt++)
                    mma16(acc[mt][nt], af[mt], bf[nt]);
        }
    };

    const int NC = K / 32;
    issue(0); cp_commit();
    issue(1); cp_commit();

    for (int c = 0; c < NC; c++) {
        cp_wait<1>();
        __syncthreads();
        if (c + 2 < NC) issue(c + 2);
        cp_commit();
        compute(c);
    }

    // ---- epilogue ----
    #pragma unroll
    for (int nt = 0; nt < 8; nt++) {
        int col = col0 + wn * 64 + nt * 8 + 2 * tig;
        float b0 = __ldg(bias + col);
        float b1 = __ldg(bias + col + 1);
        #pragma unroll
        for (int mt = 0; mt < 2; mt++) {
            int r = row0 + wm * 32 + mt * 16 + gid;
            float v0 = acc[mt][nt][0] + b0;
            float v1 = acc[mt][nt][1] + b1;
            float v2 = acc[mt][nt][2] + b0;
            float v3 = acc[mt][nt][3] + b1;
            if (RELU) {
                v0 = fmaxf(v0, 0.f); v1 = fmaxf(v1, 0.f);
                v2 = fmaxf(v2, 0.f); v3 = fmaxf(v3, 0.f);
            }
            if (OUT16) {
                __half* C = (__half*)Cv;
                if (r < M) {
                    __half2 h = __floats2half2_rn(v0, v1);
                    *reinterpret_cast<__half2*>(C + (size_t)r * Ncol + col) = h;
                }
                if (r + 8 < M) {
                    __half2 h = __floats2half2_rn(v2, v3);
                    *reinterpret_cast<__half2*>(C + (size_t)(r + 8) * Ncol + col) = h;
                }
            } else {
                float* C = (float*)Cv;
                if (r < M)
                    *reinterpret_cast<float2*>(C + (size_t)r * Ncol + col) = make_float2(v0, v1);
                if (r + 8 < M)
                    *reinterpret_cast<float2*>(C + (size_t)(r + 8) * Ncol + col) = make_float2(v2, v3);
            }
        }
    }
}

// ---------------------------------------------------------------------------
// Launch
// ---------------------------------------------------------------------------
extern "C" void kernel_launch(void* const* d_in, const int* in_sizes, int n_in,
                              void* d_out, int out_size) {
    const float* x    = (const float*)d_in[0];
    const void*  eiRaw= d_in[1];
    const float* eps0 = (const float*)d_in[2];
    const float* W1_0 = (const float*)d_in[3];
    const float* b1_0 = (const float*)d_in[4];
    const float* W2_0 = (const float*)d_in[5];
    const float* b2_0 = (const float*)d_in[6];
    const float* eps1 = (const float*)d_in[7];
    const float* W1_1 = (const float*)d_in[8];
    const float* b1_1 = (const float*)d_in[9];
    const float* W2_1 = (const float*)d_in[10];
    const float* b2_1 = (const float*)d_in[11];
    const float* Wo   = (const float*)d_in[12];
    const float* bo   = (const float*)d_in[13];
    float*       out  = (float*)d_out;

    const int two_e = in_sizes[1];
    const int E     = two_e / 2;

    __half *xh, *comb, *t1, *h0, *wq;
    int *deg, *cur, *off, *esrc, *bsum, *boff;
    cudaGetSymbolAddress((void**)&xh,   g_xh);
    cudaGetSymbolAddress((void**)&comb, g_comb);
    cudaGetSymbolAddress((void**)&t1,   g_t1);
    cudaGetSymbolAddress((void**)&h0,   g_h0);
    cudaGetSymbolAddress((void**)&wq,   g_wq);
    cudaGetSymbolAddress((void**)&deg,  g_deg);
    cudaGetSymbolAddress((void**)&cur,  g_cur);
    cudaGetSymbolAddress((void**)&off,  g_off);
    cudaGetSymbolAddress((void**)&esrc, g_esrc);
    cudaGetSymbolAddress((void**)&bsum, g_bsum);
    cudaGetSymbolAddress((void**)&boff, g_boff);

    __half* W1_0t = wq;                   // [256][128]
    __half* W2_0t = wq + 32768;           // [256][256]
    __half* W1_1t = wq + 98304;           // [256][256]
    __half* W2_1t = wq + 163840;          // [256][256]
    __half* Wot   = wq + 229376;          // [128][256]

    cudaFuncSetAttribute(gemm_fp16<true,  true >,
                         cudaFuncAttributeMaxDynamicSharedMemorySize, GEMM_SMEM_BYTES);
    cudaFuncSetAttribute(gemm_fp16<false, true >,
                         cudaFuncAttributeMaxDynamicSharedMemorySize, GEMM_SMEM_BYTES);
    cudaFuncSetAttribute(gemm_fp16<false, false>,
                         cudaFuncAttributeMaxDynamicSharedMemorySize, GEMM_SMEM_BYTES);

    // ---- detect edge dtype ----
    int nscan = two_e < 128 ? two_e : 128;
    detect_kernel<<<1, 32>>>(eiRaw, nscan);

    // ---- CSR build ----
    zero_int_kernel<<<(N_NODES + 255) / 256, 256>>>(deg, N_NODES);
    hist_kernel<<<(E + 255) / 256, 256>>>(eiRaw, deg, E);
    scan_p1<<<SCAN_NB, SCAN_B>>>(deg, bsum);
    scan_p2<<<1, 256>>>(bsum, boff);
    scan_p3<<<SCAN_NB, SCAN_B>>>(deg, boff, off, cur);
    fill_kernel<<<(E + 255) / 256, 256>>>(eiRaw, cur, esrc, E);

    // ---- quantize: x -> fp16, weights -> fp16 transposed ----
    quantx_kernel<<<(N_NODES * D_IN / 2 + 255) / 256, 256>>>((const float2*)x, (__half2*)xh,
                                                             N_NODES * D_IN / 2);
    quantw_all<<<1024, 256>>>(W1_0, W2_0, W1_1, W2_1, Wo, wq);

    dim3 gH((N_NODES + 127) / 128, 2);   // Ncol=256
    dim3 gO((N_NODES + 127) / 128, 1);   // Ncol=128
    int  gGather = (N_NODES + 7) / 8;

    // ---- layer 0 ----
    gather_h<128><<<gGather, 256>>>(xh, off, esrc, eps0, comb);
    gemm_fp16<true,  true ><<<gH, 256, GEMM_SMEM_BYTES>>>(comb, W1_0t, b1_0, t1, N_NODES, D_IN,  D_HID);
    gemm_fp16<false, true ><<<gH, 256, GEMM_SMEM_BYTES>>>(t1,   W2_0t, b2_0, h0, N_NODES, D_HID, D_HID);

    // ---- layer 1 ----
    gather_h<256><<<gGather, 256>>>(h0, off, esrc, eps1, comb);
    gemm_fp16<true,  true ><<<gH, 256, GEMM_SMEM_BYTES>>>(comb, W1_1t, b1_1, t1, N_NODES, D_HID, D_HID);
    gemm_fp16<false, true ><<<gH, 256, GEMM_SMEM_BYTES>>>(t1,   W2_1t, b2_1, h0, N_NODES, D_HID, D_HID); // h1

    // ---- fc_out (fp32 out) ----
    gemm_fp16<false, false><<<gO, 256, GEMM_SMEM_BYTES>>>(h0, Wot, bo, out, N_NODES, D_HID, D_IN);
}